// round 12
// baseline (speedup 1.0000x reference)
#include <cuda_runtime.h>

#define CC 1024
#define HH 16
#define KK 7
#define PADL 3
#define TT 4096
#define BB 8
#define T_TILE 64
#define CHUNK 8
#define NCHUNK (T_TILE / CHUNK)
#define C4 (CC / 4)          // 256 float4 lanes across channels
#define THREADS 128          // half of C4 per block; blockIdx.z picks half

template <bool GUARD>
__device__ __forceinline__
void run_tile(const float4* __restrict__ xp, float4* __restrict__ yp,
              const float4 (&wk)[KK], int t0) {
    const float4 zero = make_float4(0.f, 0.f, 0.f, 0.f);

    // carry window: win[k] = x[t0 - 3 + k], k = 0..5
    float4 win[KK - 1];
    #pragma unroll
    for (int k = 0; k < KK - 1; k++) {
        const int tt = t0 - PADL + k;
        win[k] = (!GUARD || tt >= 0) ? xp[(size_t)tt * C4] : zero;
    }

    #pragma unroll
    for (int c = 0; c < NCHUNK; c++) {
        const int tbase = t0 + c * CHUNK;

        // ---- front-batched independent loads: x[tbase+3 .. tbase+10] ----
        float4 buf[CHUNK];
        #pragma unroll
        for (int j = 0; j < CHUNK; j++) {
            const int tt = tbase + PADL + j;
            buf[j] = (!GUARD || tt < TT) ? xp[(size_t)tt * C4] : zero;
        }

        // ---- compute & store 8 outputs ----
        #pragma unroll
        for (int j = 0; j < CHUNK; j++) {
            float4 acc = zero;
            #pragma unroll
            for (int k = 0; k < KK; k++) {
                const int i = j + k;                  // compile-time constant
                const float4 v = (i < KK - 1) ? win[i] : buf[i - (KK - 1)];
                acc.x = fmaf(v.x, wk[k].x, acc.x);
                acc.y = fmaf(v.y, wk[k].y, acc.y);
                acc.z = fmaf(v.z, wk[k].z, acc.z);
                acc.w = fmaf(v.w, wk[k].w, acc.w);
            }
            yp[(size_t)(tbase + j) * C4] = acc;
        }

        // next chunk's carry window = buf[2..7]
        #pragma unroll
        for (int k = 0; k < KK - 1; k++) win[k] = buf[k + 2];
    }
}

__global__ __launch_bounds__(THREADS, 4)
void lwconv1d_kernel(const float* __restrict__ x,
                     const float* __restrict__ w,
                     float* __restrict__ y) {
    const int c4 = blockIdx.z * THREADS + threadIdx.x;   // 0..255
    const int t0 = blockIdx.x * T_TILE;
    const int b  = blockIdx.y;

    // ---- per-lane softmaxed taps for its 4 channels (head = channel & 15) ----
    float4 wk[KK];
    {
        float tmp[4][KK];
        #pragma unroll
        for (int j = 0; j < 4; j++) {
            const int h = ((c4 << 2) + j) & (HH - 1);
            float m = -1e30f;
            #pragma unroll
            for (int k = 0; k < KK; k++) {
                tmp[j][k] = __ldg(&w[h * KK + k]);
                m = fmaxf(m, tmp[j][k]);
            }
            float s = 0.f;
            #pragma unroll
            for (int k = 0; k < KK; k++) {
                tmp[j][k] = __expf(tmp[j][k] - m);
                s += tmp[j][k];
            }
            const float inv = 1.f / s;
            #pragma unroll
            for (int k = 0; k < KK; k++) tmp[j][k] *= inv;
        }
        #pragma unroll
        for (int k = 0; k < KK; k++)
            wk[k] = make_float4(tmp[0][k], tmp[1][k], tmp[2][k], tmp[3][k]);
    }

    const float4* __restrict__ xp =
        reinterpret_cast<const float4*>(x + (size_t)b * TT * CC) + c4;
    float4* __restrict__ yp =
        reinterpret_cast<float4*>(y + (size_t)b * TT * CC) + c4;

    // interior tiles need no boundary predicates (63/64 of all CTAs)
    if (t0 >= PADL && t0 + T_TILE + PADL <= TT) {
        run_tile<false>(xp, yp, wk, t0);
    } else {
        run_tile<true>(xp, yp, wk, t0);
    }
}

extern "C" void kernel_launch(void* const* d_in, const int* in_sizes, int n_in,
                              void* d_out, int out_size) {
    const float* x = (const float*)d_in[0];   // (8, 4096, 1024) f32
    const float* w = (const float*)d_in[1];   // (16, 1, 7) f32
    float* y = (float*)d_out;                 // (8, 4096, 1024) f32

    dim3 grid(TT / T_TILE, BB, C4 / THREADS); // (64, 8, 2) = 1024 CTAs
    dim3 block(THREADS);                      // 128
    lwconv1d_kernel<<<grid, block>>>(x, w, y);
}

// round 13
// speedup vs baseline: 1.0434x; 1.0434x over previous
#include <cuda_runtime.h>

#define CC 1024
#define HH 16
#define KK 7
#define PADL 3
#define TT 4096
#define BB 8
#define T_TILE 32
#define CHUNK 8
#define NCHUNK (T_TILE / CHUNK)
#define C4 (CC / 4)          // 256 float4 lanes across channels
#define THREADS 128          // half of C4 per block; blockIdx.z picks half

template <bool GUARD>
__device__ __forceinline__
void run_tile(const float4* __restrict__ xp, float4* __restrict__ yp,
              const float4 (&wk)[KK], int t0) {
    const float4 zero = make_float4(0.f, 0.f, 0.f, 0.f);

    // carry window: win[k] = x[t0 - 3 + k], k = 0..5
    float4 win[KK - 1];
    #pragma unroll
    for (int k = 0; k < KK - 1; k++) {
        const int tt = t0 - PADL + k;
        win[k] = (!GUARD || tt >= 0) ? xp[(size_t)tt * C4] : zero;
    }

    #pragma unroll
    for (int c = 0; c < NCHUNK; c++) {
        const int tbase = t0 + c * CHUNK;

        // ---- front-batched independent loads: x[tbase+3 .. tbase+10] ----
        float4 buf[CHUNK];
        #pragma unroll
        for (int j = 0; j < CHUNK; j++) {
            const int tt = tbase + PADL + j;
            buf[j] = (!GUARD || tt < TT) ? xp[(size_t)tt * C4] : zero;
        }

        // ---- compute & store 8 outputs ----
        #pragma unroll
        for (int j = 0; j < CHUNK; j++) {
            float4 acc = zero;
            #pragma unroll
            for (int k = 0; k < KK; k++) {
                const int i = j + k;                  // compile-time constant
                const float4 v = (i < KK - 1) ? win[i] : buf[i - (KK - 1)];
                acc.x = fmaf(v.x, wk[k].x, acc.x);
                acc.y = fmaf(v.y, wk[k].y, acc.y);
                acc.z = fmaf(v.z, wk[k].z, acc.z);
                acc.w = fmaf(v.w, wk[k].w, acc.w);
            }
            yp[(size_t)(tbase + j) * C4] = acc;
        }

        // next chunk's carry window = buf[2..7]
        #pragma unroll
        for (int k = 0; k < KK - 1; k++) win[k] = buf[k + 2];
    }
}

__global__ __launch_bounds__(THREADS, 4)
void lwconv1d_kernel(const float* __restrict__ x,
                     const float* __restrict__ w,
                     float* __restrict__ y) {
    const int c4 = blockIdx.z * THREADS + threadIdx.x;   // 0..255
    const int t0 = blockIdx.x * T_TILE;
    const int b  = blockIdx.y;

    // ---- per-lane softmaxed taps for its 4 channels (head = channel & 15) ----
    float4 wk[KK];
    {
        float tmp[4][KK];
        #pragma unroll
        for (int j = 0; j < 4; j++) {
            const int h = ((c4 << 2) + j) & (HH - 1);
            float m = -1e30f;
            #pragma unroll
            for (int k = 0; k < KK; k++) {
                tmp[j][k] = __ldg(&w[h * KK + k]);
                m = fmaxf(m, tmp[j][k]);
            }
            float s = 0.f;
            #pragma unroll
            for (int k = 0; k < KK; k++) {
                tmp[j][k] = __expf(tmp[j][k] - m);
                s += tmp[j][k];
            }
            const float inv = 1.f / s;
            #pragma unroll
            for (int k = 0; k < KK; k++) tmp[j][k] *= inv;
        }
        #pragma unroll
        for (int k = 0; k < KK; k++)
            wk[k] = make_float4(tmp[0][k], tmp[1][k], tmp[2][k], tmp[3][k]);
    }

    const float4* __restrict__ xp =
        reinterpret_cast<const float4*>(x + (size_t)b * TT * CC) + c4;
    float4* __restrict__ yp =
        reinterpret_cast<float4*>(y + (size_t)b * TT * CC) + c4;

    // interior tiles need no boundary predicates (126/128 of all CTAs)
    if (t0 >= PADL && t0 + T_TILE + PADL <= TT) {
        run_tile<false>(xp, yp, wk, t0);
    } else {
        run_tile<true>(xp, yp, wk, t0);
    }
}

extern "C" void kernel_launch(void* const* d_in, const int* in_sizes, int n_in,
                              void* d_out, int out_size) {
    const float* x = (const float*)d_in[0];   // (8, 4096, 1024) f32
    const float* w = (const float*)d_in[1];   // (16, 1, 7) f32
    float* y = (float*)d_out;                 // (8, 4096, 1024) f32

    dim3 grid(TT / T_TILE, BB, C4 / THREADS); // (128, 8, 2) = 2048 CTAs
    dim3 block(THREADS);                      // 128
    lwconv1d_kernel<<<grid, block>>>(x, w, y);
}

// round 14
// speedup vs baseline: 1.0808x; 1.0358x over previous
#include <cuda_runtime.h>

#define CC 1024
#define HH 16
#define KK 7
#define PADL 3
#define TT 4096
#define BB 8
#define T_TILE 32
#define CHUNK 8
#define NCHUNK (T_TILE / CHUNK)
#define C4 (CC / 4)          // 256 float4 lanes across channels
#define THREADS 128          // half of C4 per block; blockIdx.z picks half

template <bool GUARD>
__device__ __forceinline__
void run_tile(const float4* __restrict__ xp, float4* __restrict__ yp,
              const float4 (&wk)[KK], int t0) {
    const float4 zero = make_float4(0.f, 0.f, 0.f, 0.f);

    // carry window: win[k] = x[t0 - 3 + k], k = 0..5
    float4 win[KK - 1];
    #pragma unroll
    for (int k = 0; k < KK - 1; k++) {
        const int tt = t0 - PADL + k;
        win[k] = (!GUARD || tt >= 0) ? xp[(size_t)tt * C4] : zero;
    }

    #pragma unroll
    for (int c = 0; c < NCHUNK; c++) {
        const int tbase = t0 + c * CHUNK;

        // ---- front-batched independent loads: x[tbase+3 .. tbase+10] ----
        float4 buf[CHUNK];
        #pragma unroll
        for (int j = 0; j < CHUNK; j++) {
            const int tt = tbase + PADL + j;
            buf[j] = (!GUARD || tt < TT) ? xp[(size_t)tt * C4] : zero;
        }

        // ---- compute & store 8 outputs ----
        #pragma unroll
        for (int j = 0; j < CHUNK; j++) {
            float4 acc = zero;
            #pragma unroll
            for (int k = 0; k < KK; k++) {
                const int i = j + k;                  // compile-time constant
                const float4 v = (i < KK - 1) ? win[i] : buf[i - (KK - 1)];
                acc.x = fmaf(v.x, wk[k].x, acc.x);
                acc.y = fmaf(v.y, wk[k].y, acc.y);
                acc.z = fmaf(v.z, wk[k].z, acc.z);
                acc.w = fmaf(v.w, wk[k].w, acc.w);
            }
            yp[(size_t)(tbase + j) * C4] = acc;
        }

        // next chunk's carry window = buf[2..7]
        #pragma unroll
        for (int k = 0; k < KK - 1; k++) win[k] = buf[k + 2];
    }
}

__global__ __launch_bounds__(THREADS, 4)
void lwconv1d_kernel(const float* __restrict__ x,
                     const float* __restrict__ w,
                     float* __restrict__ y) {
    // transposed softmaxed taps: s_w[k][h], 16 heads per row -> LDS.128-friendly
    __shared__ float s_w[KK][HH];

    const int tid = threadIdx.x;
    const int c4 = blockIdx.z * THREADS + tid;           // 0..255
    const int t0 = blockIdx.x * T_TILE;
    const int b  = blockIdx.y;

    // ---- lanes 0..15 of warp 0 compute the 16 head softmaxes ----
    if (tid < HH) {
        float t[KK];
        float m = -1e30f;
        #pragma unroll
        for (int k = 0; k < KK; k++) {
            t[k] = __ldg(&w[tid * KK + k]);
            m = fmaxf(m, t[k]);
        }
        float s = 0.f;
        #pragma unroll
        for (int k = 0; k < KK; k++) {
            t[k] = __expf(t[k] - m);
            s += t[k];
        }
        const float inv = 1.f / s;
        #pragma unroll
        for (int k = 0; k < KK; k++) s_w[k][tid] = t[k] * inv;
    }
    __syncthreads();

    // ---- each thread's 4 channels are 4 consecutive heads: (4*c4) mod 16 ----
    const int h0 = (c4 << 2) & (HH - 1);                 // multiple of 4 -> 16B aligned
    float4 wk[KK];
    #pragma unroll
    for (int k = 0; k < KK; k++)
        wk[k] = *reinterpret_cast<const float4*>(&s_w[k][h0]);

    const float4* __restrict__ xp =
        reinterpret_cast<const float4*>(x + (size_t)b * TT * CC) + c4;
    float4* __restrict__ yp =
        reinterpret_cast<float4*>(y + (size_t)b * TT * CC) + c4;

    // interior tiles need no boundary predicates (126/128 of all CTAs)
    if (t0 >= PADL && t0 + T_TILE + PADL <= TT) {
        run_tile<false>(xp, yp, wk, t0);
    } else {
        run_tile<true>(xp, yp, wk, t0);
    }
}

extern "C" void kernel_launch(void* const* d_in, const int* in_sizes, int n_in,
                              void* d_out, int out_size) {
    const float* x = (const float*)d_in[0];   // (8, 4096, 1024) f32
    const float* w = (const float*)d_in[1];   // (16, 1, 7) f32
    float* y = (float*)d_out;                 // (8, 4096, 1024) f32

    dim3 grid(TT / T_TILE, BB, C4 / THREADS); // (128, 8, 2) = 2048 CTAs
    dim3 block(THREADS);                      // 128
    lwconv1d_kernel<<<grid, block>>>(x, w, y);
}